// round 6
// baseline (speedup 1.0000x reference)
#include <cuda_runtime.h>

// x: [8, 256, 16, 56, 56] fp32, weight: [256, 1, 3] fp32
// y[n,c,t,h,w] = w0*x[t-2] + w1*x[t] + w2*x[t+2]  (zero outside t range)
//
// Dilation-2 stencil decouples even and odd t. Each thread owns one
// (nc, parity, hw4-chunk): an 8-plane sub-line, radius-1 stencil, all
// planes front-batched. Streaming (.cs) on both loads and stores.
// __launch_bounds__(256, 6) caps regs at 42 -> 6 blocks/SM, recovering the
// occupancy lost to .cs's register cost while keeping the cache policy.

__global__ __launch_bounds__(256, 6) void tshift_kernel(
    const float* __restrict__ x,
    const float* __restrict__ w,
    float* __restrict__ y)
{
    constexpr int HW4  = 3136 / 4;     // 784 float4 per t-plane
    constexpr int THW4 = 16 * HW4;     // float4 per (n,c) line
    constexpr int TS   = 8;            // sub-line length (even or odd t)

    int idx = blockIdx.x * blockDim.x + threadIdx.x;  // 0 .. 2048*2*784-1 exactly
    int sub = idx / HW4;               // 0 .. 4095  (nc*2 + parity)
    int q   = idx - sub * HW4;
    int nc  = sub >> 1;
    int par = sub & 1;
    int c   = nc & 255;

    float w0 = __ldg(&w[c * 3 + 0]);
    float w1 = __ldg(&w[c * 3 + 1]);
    float w2 = __ldg(&w[c * 3 + 2]);

    long base = (long)nc * THW4 + (long)par * HW4 + q;
    const float4* xp = reinterpret_cast<const float4*>(x) + base;
    float4*       yp = reinterpret_cast<float4*>(y) + base;

    // Front-batch the sub-line: up to 8 independent LDG.128.cs in flight.
    float4 xv[TS];
#pragma unroll
    for (int i = 0; i < TS; i++)
        xv[i] = __ldcs(xp + (long)(2 * i) * HW4);

#pragma unroll
    for (int i = 0; i < TS; i++) {
        float4 r;
        r.x = w1 * xv[i].x;
        r.y = w1 * xv[i].y;
        r.z = w1 * xv[i].z;
        r.w = w1 * xv[i].w;
        if (i >= 1) {
            r.x = fmaf(w0, xv[i - 1].x, r.x);
            r.y = fmaf(w0, xv[i - 1].y, r.y);
            r.z = fmaf(w0, xv[i - 1].z, r.z);
            r.w = fmaf(w0, xv[i - 1].w, r.w);
        }
        if (i < TS - 1) {
            r.x = fmaf(w2, xv[i + 1].x, r.x);
            r.y = fmaf(w2, xv[i + 1].y, r.y);
            r.z = fmaf(w2, xv[i + 1].z, r.z);
            r.w = fmaf(w2, xv[i + 1].w, r.w);
        }
        __stcs(yp + (long)(2 * i) * HW4, r);
    }
}

extern "C" void kernel_launch(void* const* d_in, const int* in_sizes, int n_in,
                              void* d_out, int out_size)
{
    const float* x = (const float*)d_in[0];
    const float* w = (const float*)d_in[1];
    float* y = (float*)d_out;

    // total threads = 2048 * 2 * 784 = 3,211,264 -> 12544 blocks of 256 (exact)
    constexpr int total   = 2048 * 2 * 784;
    constexpr int threads = 256;
    constexpr int blocks  = total / threads;
    tshift_kernel<<<blocks, threads>>>(x, w, y);
}

// round 7
// speedup vs baseline: 1.0317x; 1.0317x over previous
#include <cuda_runtime.h>

// x: [8, 256, 16, 56, 56] fp32, weight: [256, 1, 3] fp32
// y[n,c,t,h,w] = w0*x[t-2] + w1*x[t] + w2*x[t+2]  (zero outside t range)
//
// Dilation-2 stencil decouples even and odd t. Each thread owns one
// (nc, parity, hw4-chunk): an 8-plane sub-line, radius-1 stencil, all
// planes front-batched (MLP=8). Streaming (.cs) on both loads and stores.
// All index math in 32-bit (tensor is 411MB; offsets fit uint32) to trim
// address registers; natural register allocation (no launch-bounds cap —
// forcing occupancy was shown to regress).

__global__ __launch_bounds__(256) void tshift_kernel(
    const float* __restrict__ x,
    const float* __restrict__ w,
    float* __restrict__ y)
{
    constexpr unsigned HW4  = 3136u / 4u;   // 784 float4 per t-plane
    constexpr unsigned THW4 = 16u * HW4;    // float4 per (n,c) line
    constexpr int TS = 8;                   // sub-line length (even or odd t)

    unsigned idx = blockIdx.x * blockDim.x + threadIdx.x;  // 0 .. 2048*2*784-1
    unsigned sub = idx / HW4;               // nc*2 + parity
    unsigned q   = idx - sub * HW4;
    unsigned nc  = sub >> 1;
    unsigned par = sub & 1u;
    unsigned c   = nc & 255u;

    float w0 = __ldg(&w[c * 3u + 0u]);
    float w1 = __ldg(&w[c * 3u + 1u]);
    float w2 = __ldg(&w[c * 3u + 2u]);

    unsigned base = nc * THW4 + par * HW4 + q;   // float4 index, fits 32-bit
    const float4* xp = reinterpret_cast<const float4*>(x) + base;
    float4*       yp = reinterpret_cast<float4*>(y) + base;

    // Front-batch the whole sub-line: 8 independent LDG.128.cs in flight.
    float4 xv[TS];
#pragma unroll
    for (int i = 0; i < TS; i++)
        xv[i] = __ldcs(xp + (unsigned)(2 * i) * HW4);

#pragma unroll
    for (int i = 0; i < TS; i++) {
        float4 r;
        r.x = w1 * xv[i].x;
        r.y = w1 * xv[i].y;
        r.z = w1 * xv[i].z;
        r.w = w1 * xv[i].w;
        if (i >= 1) {
            r.x = fmaf(w0, xv[i - 1].x, r.x);
            r.y = fmaf(w0, xv[i - 1].y, r.y);
            r.z = fmaf(w0, xv[i - 1].z, r.z);
            r.w = fmaf(w0, xv[i - 1].w, r.w);
        }
        if (i < TS - 1) {
            r.x = fmaf(w2, xv[i + 1].x, r.x);
            r.y = fmaf(w2, xv[i + 1].y, r.y);
            r.z = fmaf(w2, xv[i + 1].z, r.z);
            r.w = fmaf(w2, xv[i + 1].w, r.w);
        }
        __stcs(yp + (unsigned)(2 * i) * HW4, r);
    }
}

extern "C" void kernel_launch(void* const* d_in, const int* in_sizes, int n_in,
                              void* d_out, int out_size)
{
    const float* x = (const float*)d_in[0];
    const float* w = (const float*)d_in[1];
    float* y = (float*)d_out;

    // total threads = 2048 * 2 * 784 = 3,211,264 -> 12544 blocks of 256 (exact)
    constexpr int total   = 2048 * 2 * 784;
    constexpr int threads = 256;
    constexpr int blocks  = total / threads;
    tshift_kernel<<<blocks, threads>>>(x, w, y);
}

// round 8
// speedup vs baseline: 1.0433x; 1.0112x over previous
#include <cuda_runtime.h>

// x: [8, 256, 16, 56, 56] fp32, weight: [256, 1, 3] fp32
// y[n,c,t,h,w] = w0*x[t-2] + w1*x[t] + w2*x[t+2]  (zero outside t range)
//
// Dilation-2 stencil decouples even and odd t. Each thread owns one
// (nc, parity, hw4-chunk): an 8-plane sub-line, radius-1 stencil, planes
// front-batched (MLP=8), streaming (.cs) loads and stores, uint32 indexing.
//
// Dead-plane elimination: plane xv[j] feeds y[j+1] (w0), y[j] (w1),
// y[j-1] (w2). If every weight that consumes it is zero (warp-uniform test;
// true for the edge planes of the one-hot shift weight), skip the load and
// substitute zeros — correct for arbitrary weights, fewer bytes for this one.

__global__ __launch_bounds__(256) void tshift_kernel(
    const float* __restrict__ x,
    const float* __restrict__ w,
    float* __restrict__ y)
{
    constexpr unsigned HW4  = 3136u / 4u;   // 784 float4 per t-plane
    constexpr unsigned THW4 = 16u * HW4;    // float4 per (n,c) line
    constexpr int TS = 8;                   // sub-line length (even or odd t)

    unsigned idx = blockIdx.x * blockDim.x + threadIdx.x;  // 0 .. 2048*2*784-1
    unsigned sub = idx / HW4;               // nc*2 + parity
    unsigned q   = idx - sub * HW4;
    unsigned nc  = sub >> 1;
    unsigned par = sub & 1u;
    unsigned c   = nc & 255u;

    float w0 = __ldg(&w[c * 3u + 0u]);
    float w1 = __ldg(&w[c * 3u + 1u]);
    float w2 = __ldg(&w[c * 3u + 2u]);

    bool u0 = (w0 != 0.0f);
    bool u1 = (w1 != 0.0f);
    bool u2 = (w2 != 0.0f);

    unsigned base = nc * THW4 + par * HW4 + q;   // float4 index, fits 32-bit
    const float4* xp = reinterpret_cast<const float4*>(x) + base;
    float4*       yp = reinterpret_cast<float4*>(y) + base;

    // Front-batch the sub-line; predicate off planes no nonzero weight uses.
    float4 xv[TS];
#pragma unroll
    for (int j = 0; j < TS; j++) {
        bool need = (u0 && j < TS - 1) || u1 || (u2 && j > 0);
        if (need)
            xv[j] = __ldcs(xp + (unsigned)(2 * j) * HW4);
        else
            xv[j] = make_float4(0.f, 0.f, 0.f, 0.f);
    }

#pragma unroll
    for (int i = 0; i < TS; i++) {
        float4 r;
        r.x = w1 * xv[i].x;
        r.y = w1 * xv[i].y;
        r.z = w1 * xv[i].z;
        r.w = w1 * xv[i].w;
        if (i >= 1) {
            r.x = fmaf(w0, xv[i - 1].x, r.x);
            r.y = fmaf(w0, xv[i - 1].y, r.y);
            r.z = fmaf(w0, xv[i - 1].z, r.z);
            r.w = fmaf(w0, xv[i - 1].w, r.w);
        }
        if (i < TS - 1) {
            r.x = fmaf(w2, xv[i + 1].x, r.x);
            r.y = fmaf(w2, xv[i + 1].y, r.y);
            r.z = fmaf(w2, xv[i + 1].z, r.z);
            r.w = fmaf(w2, xv[i + 1].w, r.w);
        }
        __stcs(yp + (unsigned)(2 * i) * HW4, r);
    }
}

extern "C" void kernel_launch(void* const* d_in, const int* in_sizes, int n_in,
                              void* d_out, int out_size)
{
    const float* x = (const float*)d_in[0];
    const float* w = (const float*)d_in[1];
    float* y = (float*)d_out;

    // total threads = 2048 * 2 * 784 = 3,211,264 -> 12544 blocks of 256 (exact)
    constexpr int total   = 2048 * 2 * 784;
    constexpr int threads = 256;
    constexpr int blocks  = total / threads;
    tshift_kernel<<<blocks, threads>>>(x, w, y);
}